// round 6
// baseline (speedup 1.0000x reference)
#include <cuda_runtime.h>
#include <math.h>

#define HIN 1536
#define BM  128
#define BK  16
#define NT  (HIN / BK)   // 96 k-tiles

using u64 = unsigned long long;

__device__ __forceinline__ u64 pk2(float lo, float hi) {
    u64 r; asm("mov.b64 %0, {%1, %2};" : "=l"(r) : "f"(lo), "f"(hi)); return r;
}
__device__ __forceinline__ void upk2(u64 v, float& lo, float& hi) {
    asm("mov.b64 {%0, %1}, %2;" : "=f"(lo), "=f"(hi) : "l"(v));
}
__device__ __forceinline__ u64 ffma2(u64 a, u64 b, u64 c) {
#if defined(__CUDA_ARCH__) && (__CUDA_ARCH__ >= 1000)
    u64 d; asm("fma.rn.f32x2 %0, %1, %2, %3;" : "=l"(d) : "l"(a), "l"(b), "l"(c)); return d;
#else
    float al, ah, bl, bh, cl, ch;
    upk2(a, al, ah); upk2(b, bl, bh); upk2(c, cl, ch);
    return pk2(fmaf(al, bl, cl), fmaf(ah, bh, ch));
#endif
}

// Per-stage smem strides (sized for max D=64)
#define AS_ST 2048   // 16*128 floats = 8 KB
#define BS_ST 1024   // 16*64 u64    = 8 KB

// Swizzled A index: physical = k*BM + (m ^ ((k>>2)<<3)).
// - stores: bank = r[0:2] | (r[3:4]^c4) -> 32 distinct banks per warp, conflict-free
// - reads: per-k quads at (ty*8)^msk stay 16B-contiguous & aligned; 2 bcast addrs/warp

template<int D>
__device__ __forceinline__ void run_stream(
    const float* __restrict__ X, const float* __restrict__ W,
    const float* __restrict__ Bias, const float* __restrict__ Gam, const float* __restrict__ Bet,
    float* __restrict__ OUT, int tile, float* __restrict__ AsF, u64* __restrict__ Bs)
{
    constexpr int TN = D / 16;            // 4 / 2 / 1  (also = B floats per thread per tile)
    const int tid = threadIdx.x;
    const int tx  = tid & 15;             // n-group
    const int ty  = tid >> 4;             // m-group: rows ty*8 .. ty*8+7
    const int r0  = tid >> 2;             // A-load row base (+p*64)
    const int c4  = tid & 3;              // A-load k-chunk
    const float* __restrict__ Ablk = X + (size_t)tile * BM * HIN;

    float4 va[2];
    float  vb[TN];
    u64 acc[4][TN];
#pragma unroll
    for (int i = 0; i < 4; ++i)
#pragma unroll
        for (int j = 0; j < TN; ++j) acc[i][j] = 0ull;

    // ---- prologue: load + store tile 0 into stage 0 ----
#pragma unroll
    for (int p = 0; p < 2; ++p)
        va[p] = *(const float4*)(Ablk + (size_t)(r0 + p * 64) * HIN + c4 * 4);
#pragma unroll
    for (int q = 0; q < TN; ++q) vb[q] = W[tid + q * 256];

#pragma unroll
    for (int p = 0; p < 2; ++p) {
        const int r = r0 + p * 64;
        const float* vp = (const float*)&va[p];
#pragma unroll
        for (int u = 0; u < 4; ++u)
            AsF[(c4 * 4 + u) * BM + (r ^ (c4 << 3))] = vp[u];
    }
#pragma unroll
    for (int q = 0; q < TN; ++q) { int idx = tid + q * 256; Bs[idx] = pk2(vb[q], vb[q]); }
    __syncthreads();

    int cur = 0;
    for (int t = 0; t < NT; ++t) {
        const bool more = (t + 1 < NT);
        const int k0n = (t + 1) * BK;
        if (more) {
#pragma unroll
            for (int p = 0; p < 2; ++p)
                va[p] = *(const float4*)(Ablk + (size_t)(r0 + p * 64) * HIN + k0n + c4 * 4);
#pragma unroll
            for (int q = 0; q < TN; ++q) vb[q] = W[(size_t)k0n * D + tid + q * 256];
        }
        const float* Ac = AsF + cur * AS_ST;
        const u64*   Bc = Bs  + cur * BS_ST;

        // ---- first half: k = 0..7 ----
#pragma unroll
        for (int k = 0; k < 8; ++k) {
            const int msk = (k >> 2) << 3;
            ulonglong2 a0 = *(const ulonglong2*)(Ac + k * BM + ((ty * 8)     ^ msk));
            ulonglong2 a1 = *(const ulonglong2*)(Ac + k * BM + ((ty * 8 + 4) ^ msk));
            u64 ap[4] = { a0.x, a0.y, a1.x, a1.y };
            u64 bd[TN];
            const u64* brow = Bc + k * D + tx * TN;
            if constexpr (TN == 4) {
                ulonglong2 p0 = *(const ulonglong2*)(brow);
                ulonglong2 p1 = *(const ulonglong2*)(brow + 2);
                bd[0] = p0.x; bd[1] = p0.y; bd[2] = p1.x; bd[3] = p1.y;
            } else if constexpr (TN == 2) {
                ulonglong2 p0 = *(const ulonglong2*)(brow);
                bd[0] = p0.x; bd[1] = p0.y;
            } else {
                bd[0] = brow[0];
            }
#pragma unroll
            for (int j = 0; j < TN; ++j)
#pragma unroll
                for (int i = 0; i < 4; ++i)
                    acc[i][j] = ffma2(ap[i], bd[j], acc[i][j]);
        }

        // ---- mid-tile: stage next tile into the other buffer (STS retire during 2nd half) ----
        if (more) {
            float* An = AsF + (cur ^ 1) * AS_ST;
            u64*   Bn = Bs  + (cur ^ 1) * BS_ST;
#pragma unroll
            for (int p = 0; p < 2; ++p) {
                const int r = r0 + p * 64;
                const float* vp = (const float*)&va[p];
#pragma unroll
                for (int u = 0; u < 4; ++u)
                    An[(c4 * 4 + u) * BM + (r ^ (c4 << 3))] = vp[u];
            }
#pragma unroll
            for (int q = 0; q < TN; ++q) { int idx = tid + q * 256; Bn[idx] = pk2(vb[q], vb[q]); }
        }

        // ---- second half: k = 8..15 ----
#pragma unroll
        for (int k = 8; k < 16; ++k) {
            const int msk = (k >> 2) << 3;
            ulonglong2 a0 = *(const ulonglong2*)(Ac + k * BM + ((ty * 8)     ^ msk));
            ulonglong2 a1 = *(const ulonglong2*)(Ac + k * BM + ((ty * 8 + 4) ^ msk));
            u64 ap[4] = { a0.x, a0.y, a1.x, a1.y };
            u64 bd[TN];
            const u64* brow = Bc + k * D + tx * TN;
            if constexpr (TN == 4) {
                ulonglong2 p0 = *(const ulonglong2*)(brow);
                ulonglong2 p1 = *(const ulonglong2*)(brow + 2);
                bd[0] = p0.x; bd[1] = p0.y; bd[2] = p1.x; bd[3] = p1.y;
            } else if constexpr (TN == 2) {
                ulonglong2 p0 = *(const ulonglong2*)(brow);
                bd[0] = p0.x; bd[1] = p0.y;
            } else {
                bd[0] = brow[0];
            }
#pragma unroll
            for (int j = 0; j < TN; ++j)
#pragma unroll
                for (int i = 0; i < 4; ++i)
                    acc[i][j] = ffma2(ap[i], bd[j], acc[i][j]);
        }
        __syncthreads();
        cur ^= 1;
    }

    // ---- fused epilogue: bias + exact GELU + LayerNorm over D + gamma/beta ----
    float bias[TN], gam[TN], bet[TN];
#pragma unroll
    for (int j = 0; j < TN; ++j) {
        int n = tx * TN + j;
        bias[j] = __ldg(Bias + n); gam[j] = __ldg(Gam + n); bet[j] = __ldg(Bet + n);
    }
    const float invD = 1.0f / (float)D;
#pragma unroll
    for (int r = 0; r < 8; ++r) {
        float v[TN];
#pragma unroll
        for (int j = 0; j < TN; ++j) {
            float lo, hi; upk2(acc[r >> 1][j], lo, hi);
            v[j] = (r & 1) ? hi : lo;
        }
        float s = 0.f, s2 = 0.f;
#pragma unroll
        for (int j = 0; j < TN; ++j) {
            float x = v[j] + bias[j];
            float g = 0.5f * x * (1.0f + erff(x * 0.7071067811865475f));  // exact GELU
            v[j] = g; s += g; s2 += g * g;
        }
        // row's D columns live in one 16-lane half-warp (tx = low 4 lane bits)
#pragma unroll
        for (int o = 8; o >= 1; o >>= 1) {
            s  += __shfl_xor_sync(0xffffffffu, s,  o);
            s2 += __shfl_xor_sync(0xffffffffu, s2, o);
        }
        float mu  = s * invD;
        float var = fmaxf(s2 * invD - mu * mu, 0.0f);
        float rs  = rsqrtf(var + 1e-5f);
        int m = tile * BM + ty * 8 + r;
        float* dst = OUT + (size_t)m * D + tx * TN;
#pragma unroll
        for (int j = 0; j < TN; ++j) v[j] = (v[j] - mu) * rs * gam[j] + bet[j];
        if constexpr (TN == 4)      *(float4*)dst = make_float4(v[0], v[1], v[2], v[3]);
        else if constexpr (TN == 2) *(float2*)dst = make_float2(v[0], v[1]);
        else                        dst[0] = v[0];
    }
}

__global__ void __launch_bounds__(256, 2) fused_gemm_gelu_ln(
    const float* __restrict__ x0, const float* __restrict__ w0, const float* __restrict__ b0,
    const float* __restrict__ g0, const float* __restrict__ t0,
    const float* __restrict__ x1, const float* __restrict__ w1, const float* __restrict__ b1,
    const float* __restrict__ g1, const float* __restrict__ t1,
    const float* __restrict__ x2, const float* __restrict__ w2, const float* __restrict__ b2,
    const float* __restrict__ g2, const float* __restrict__ t2,
    const float* __restrict__ x3, const float* __restrict__ w3, const float* __restrict__ b3,
    const float* __restrict__ g3, const float* __restrict__ t3,
    float* __restrict__ out)
{
    __shared__ __align__(16) float AsF[2 * AS_ST];  // 16 KB, 2-stage transposed+swizzled A
    __shared__ __align__(16) u64  Bs[2 * BS_ST];    // 16 KB, 2-stage {w,w}-duplicated B

    // Stream pattern {0,0,1,1,3,3,2,2} (period 8): stride-148 CTA placement (148%8==4)
    // pairs heavy (D=64) blocks with light (D=16) ones on the same SM.
    const int bid  = blockIdx.x;
    const int idx  = (bid >> 1) & 3;
    const int tile = ((bid >> 3) << 1) | (bid & 1);   // 64 tiles per stream
    if (idx == 0)      run_stream<64>(x0, w0, b0, g0, t0, out,           tile, AsF, Bs);
    else if (idx == 1) run_stream<32>(x1, w1, b1, g1, t1, out + 524288,  tile, AsF, Bs);
    else if (idx == 2) run_stream<16>(x3, w3, b3, g3, t3, out + 1048576, tile, AsF, Bs);
    else               run_stream<32>(x2, w2, b2, g2, t2, out + 786432,  tile, AsF, Bs);
}

extern "C" void kernel_launch(void* const* d_in, const int* in_sizes, int n_in,
                              void* d_out, int out_size)
{
    const float* x0 = (const float*)d_in[0];
    const float* w0 = (const float*)d_in[1];
    const float* b0 = (const float*)d_in[2];
    const float* g0 = (const float*)d_in[3];
    const float* t0 = (const float*)d_in[4];
    const float* x1 = (const float*)d_in[5];
    const float* w1 = (const float*)d_in[6];
    const float* b1 = (const float*)d_in[7];
    const float* g1 = (const float*)d_in[8];
    const float* t1 = (const float*)d_in[9];
    const float* x2 = (const float*)d_in[10];
    const float* w2 = (const float*)d_in[11];
    const float* b2 = (const float*)d_in[12];
    const float* g2 = (const float*)d_in[13];
    const float* t2 = (const float*)d_in[14];
    const float* x3 = (const float*)d_in[15];
    const float* w3 = (const float*)d_in[16];
    const float* b3 = (const float*)d_in[17];
    const float* g3 = (const float*)d_in[18];
    const float* t3 = (const float*)d_in[19];
    float* out = (float*)d_out;

    fused_gemm_gelu_ln<<<256, 256>>>(
        x0, w0, b0, g0, t0,
        x1, w1, b1, g1, t1,
        x2, w2, b2, g2, t2,
        x3, w3, b3, g3, t3,
        out);
}

// round 7
// speedup vs baseline: 1.4952x; 1.4952x over previous
#include <cuda_runtime.h>
#include <math.h>

#define HIN 1536
#define BM  128
#define BK  16
#define NT  (HIN / BK)   // 96 k-tiles
#define NTHR 128

using u64 = unsigned long long;

__device__ __forceinline__ u64 pk2(float lo, float hi) {
    u64 r; asm("mov.b64 %0, {%1, %2};" : "=l"(r) : "f"(lo), "f"(hi)); return r;
}
__device__ __forceinline__ void upk2(u64 v, float& lo, float& hi) {
    asm("mov.b64 {%0, %1}, %2;" : "=f"(lo), "=f"(hi) : "l"(v));
}
__device__ __forceinline__ u64 ffma2(u64 a, u64 b, u64 c) {
#if defined(__CUDA_ARCH__) && (__CUDA_ARCH__ >= 1000)
    u64 d; asm("fma.rn.f32x2 %0, %1, %2, %3;" : "=l"(d) : "l"(a), "l"(b), "l"(c)); return d;
#else
    float al, ah, bl, bh, cl, ch;
    upk2(a, al, ah); upk2(b, bl, bh); upk2(c, cl, ch);
    return pk2(fmaf(al, bl, cl), fmaf(ah, bh, ch));
#endif
}

// A smem: physical = k*BM + (m ^ ((k>>2)<<3)).
//  - stores: bank = r[0:2] | (r[3:4]^c4-bits) -> 32 distinct banks, conflict-free
//  - reads: 4-row quads stay 16B-contiguous/aligned; 2 bcast addrs per warp -> 4-cyc LDS.128
// B smem: PLAIN floats [k][n]; read as float4 at tx*TN -> contiguous lanes, conflict-free.
//  {w,w} duplication happens in registers (ALU pipe is idle).

template<int D>
__device__ __forceinline__ void run_stream(
    const float* __restrict__ X, const float* __restrict__ W,
    const float* __restrict__ Bias, const float* __restrict__ Gam, const float* __restrict__ Bet,
    float* __restrict__ OUT, int tile, float* __restrict__ AsF, float* __restrict__ Bk)
{
    constexpr int TN = D / 16;            // 4 / 2 / 1
    constexpr int NB = (BK * D) / NTHR;   // B floats per thread per tile: 8 / 4 / 2
    constexpr int TM = 16;                // rows per thread
    const int tid = threadIdx.x;
    const int tx  = tid & 15;             // n-group (16)
    const int ty  = tid >> 4;             // m-group (8): rows ty*16 .. ty*16+15
    const int r0  = tid >> 2;             // A-load row base (+p*32)
    const int c4  = tid & 3;              // A-load k-chunk
    const float* __restrict__ Ablk = X + (size_t)tile * BM * HIN;

    float4 va[4];
    float  vb[NB];
    u64 acc[TM / 2][TN];
#pragma unroll
    for (int i = 0; i < TM / 2; ++i)
#pragma unroll
        for (int j = 0; j < TN; ++j) acc[i][j] = 0ull;

    // ---- prologue: load tile 0 ----
#pragma unroll
    for (int p = 0; p < 4; ++p)
        va[p] = *(const float4*)(Ablk + (size_t)(r0 + p * 32) * HIN + c4 * 4);
#pragma unroll
    for (int q = 0; q < NB; ++q) vb[q] = W[tid + q * NTHR];

    for (int t = 0; t < NT; ++t) {
        // store staged tile to smem
#pragma unroll
        for (int p = 0; p < 4; ++p) {
            const int r = r0 + p * 32;
            const float* vp = (const float*)&va[p];
#pragma unroll
            for (int u = 0; u < 4; ++u)
                AsF[(c4 * 4 + u) * BM + (r ^ (c4 << 3))] = vp[u];
        }
#pragma unroll
        for (int q = 0; q < NB; ++q) Bk[tid + q * NTHR] = vb[q];
        __syncthreads();

        // prefetch next tile into registers (hidden under compute)
        const bool more = (t + 1 < NT);
        const int k0n = (t + 1) * BK;
        if (more) {
#pragma unroll
            for (int p = 0; p < 4; ++p)
                va[p] = *(const float4*)(Ablk + (size_t)(r0 + p * 32) * HIN + k0n + c4 * 4);
#pragma unroll
            for (int q = 0; q < NB; ++q) vb[q] = W[(size_t)k0n * D + tid + q * NTHR];
        }

        // compute BK k-steps
#pragma unroll
        for (int k = 0; k < BK; ++k) {
            const int msk = (k >> 2) << 3;
            // B: plain contiguous read + register duplication
            u64 bd[TN];
            if constexpr (TN == 4) {
                float4 b4 = *(const float4*)(Bk + k * D + tx * 4);
                bd[0] = pk2(b4.x, b4.x); bd[1] = pk2(b4.y, b4.y);
                bd[2] = pk2(b4.z, b4.z); bd[3] = pk2(b4.w, b4.w);
            } else if constexpr (TN == 2) {
                float2 b2 = *(const float2*)(Bk + k * D + tx * 2);
                bd[0] = pk2(b2.x, b2.x); bd[1] = pk2(b2.y, b2.y);
            } else {
                float b1 = Bk[k * D + tx];
                bd[0] = pk2(b1, b1);
            }
            // A: 16 rows = 4 conflict-free LDS.128
            const float* Ar = AsF + k * BM;
            ulonglong2 a0 = *(const ulonglong2*)(Ar + ((ty * 16)      ^ msk));
            ulonglong2 a1 = *(const ulonglong2*)(Ar + ((ty * 16 + 4)  ^ msk));
            ulonglong2 a2 = *(const ulonglong2*)(Ar + ((ty * 16 + 8)  ^ msk));
            ulonglong2 a3 = *(const ulonglong2*)(Ar + ((ty * 16 + 12) ^ msk));
            u64 ap[8] = { a0.x, a0.y, a1.x, a1.y, a2.x, a2.y, a3.x, a3.y };
#pragma unroll
            for (int j = 0; j < TN; ++j)
#pragma unroll
                for (int i = 0; i < 8; ++i)
                    acc[i][j] = ffma2(ap[i], bd[j], acc[i][j]);
        }
        __syncthreads();
    }

    // ---- fused epilogue: bias + exact GELU + LayerNorm over D + gamma/beta ----
    float bias[TN], gam[TN], bet[TN];
#pragma unroll
    for (int j = 0; j < TN; ++j) {
        int n = tx * TN + j;
        bias[j] = __ldg(Bias + n); gam[j] = __ldg(Gam + n); bet[j] = __ldg(Bet + n);
    }
    const float invD = 1.0f / (float)D;
#pragma unroll
    for (int r = 0; r < TM; ++r) {
        float v[TN];
#pragma unroll
        for (int j = 0; j < TN; ++j) {
            float lo, hi; upk2(acc[r >> 1][j], lo, hi);
            v[j] = (r & 1) ? hi : lo;
        }
        float s = 0.f, s2 = 0.f;
#pragma unroll
        for (int j = 0; j < TN; ++j) {
            float x = v[j] + bias[j];
            float g = 0.5f * x * (1.0f + erff(x * 0.7071067811865475f));  // exact GELU
            v[j] = g; s += g; s2 += g * g;
        }
        // row's D columns live in one 16-lane half-warp (tx = lane&15)
#pragma unroll
        for (int o = 8; o >= 1; o >>= 1) {
            s  += __shfl_xor_sync(0xffffffffu, s,  o);
            s2 += __shfl_xor_sync(0xffffffffu, s2, o);
        }
        float mu  = s * invD;
        float var = fmaxf(s2 * invD - mu * mu, 0.0f);
        float rs  = rsqrtf(var + 1e-5f);
        int m = tile * BM + ty * TM + r;
        float* dst = OUT + (size_t)m * D + tx * TN;
#pragma unroll
        for (int j = 0; j < TN; ++j) v[j] = (v[j] - mu) * rs * gam[j] + bet[j];
        if constexpr (TN == 4)      *(float4*)dst = make_float4(v[0], v[1], v[2], v[3]);
        else if constexpr (TN == 2) *(float2*)dst = make_float2(v[0], v[1]);
        else                        dst[0] = v[0];
    }
}

__global__ void __launch_bounds__(NTHR, 4) fused_gemm_gelu_ln(
    const float* __restrict__ x0, const float* __restrict__ w0, const float* __restrict__ b0,
    const float* __restrict__ g0, const float* __restrict__ t0,
    const float* __restrict__ x1, const float* __restrict__ w1, const float* __restrict__ b1,
    const float* __restrict__ g1, const float* __restrict__ t1,
    const float* __restrict__ x2, const float* __restrict__ w2, const float* __restrict__ b2,
    const float* __restrict__ g2, const float* __restrict__ t2,
    const float* __restrict__ x3, const float* __restrict__ w3, const float* __restrict__ b3,
    const float* __restrict__ g3, const float* __restrict__ t3,
    float* __restrict__ out)
{
    __shared__ __align__(16) float AsF[BK * BM];   // 8 KB, transposed+swizzled A tile
    __shared__ __align__(16) float Bk[BK * 64];    // 4 KB, plain B tile (max D=64)
    const int s    = blockIdx.x & 3;               // interleave streams for balance
    const int tile = blockIdx.x >> 2;              // 64 tiles per stream
    if (s == 0)      run_stream<64>(x0, w0, b0, g0, t0, out,           tile, AsF, Bk);
    else if (s == 1) run_stream<32>(x1, w1, b1, g1, t1, out + 524288,  tile, AsF, Bk);
    else if (s == 2) run_stream<32>(x2, w2, b2, g2, t2, out + 786432,  tile, AsF, Bk);
    else             run_stream<16>(x3, w3, b3, g3, t3, out + 1048576, tile, AsF, Bk);
}

extern "C" void kernel_launch(void* const* d_in, const int* in_sizes, int n_in,
                              void* d_out, int out_size)
{
    const float* x0 = (const float*)d_in[0];
    const float* w0 = (const float*)d_in[1];
    const float* b0 = (const float*)d_in[2];
    const float* g0 = (const float*)d_in[3];
    const float* t0 = (const float*)d_in[4];
    const float* x1 = (const float*)d_in[5];
    const float* w1 = (const float*)d_in[6];
    const float* b1 = (const float*)d_in[7];
    const float* g1 = (const float*)d_in[8];
    const float* t1 = (const float*)d_in[9];
    const float* x2 = (const float*)d_in[10];
    const float* w2 = (const float*)d_in[11];
    const float* b2 = (const float*)d_in[12];
    const float* g2 = (const float*)d_in[13];
    const float* t2 = (const float*)d_in[14];
    const float* x3 = (const float*)d_in[15];
    const float* w3 = (const float*)d_in[16];
    const float* b3 = (const float*)d_in[17];
    const float* g3 = (const float*)d_in[18];
    const float* t3 = (const float*)d_in[19];
    float* out = (float*)d_out;

    // grid: 4 streams x (8192/128) tiles, stream-interleaved; 128-thread blocks
    fused_gemm_gelu_ln<<<256, NTHR>>>(
        x0, w0, b0, g0, t0,
        x1, w1, b1, g1, t1,
        x2, w2, b2, g2, t2,
        x3, w3, b3, g3, t3,
        out);
}

// round 10
// speedup vs baseline: 1.6447x; 1.1000x over previous
#include <cuda_runtime.h>
#include <math.h>

#define HIN 1536
#define BM  128
#define BK  16
#define NT  (HIN / BK)   // 96 k-tiles
#define NTHR 256

using u64 = unsigned long long;

__device__ __forceinline__ u64 pk2(float lo, float hi) {
    u64 r; asm("mov.b64 %0, {%1, %2};" : "=l"(r) : "f"(lo), "f"(hi)); return r;
}
__device__ __forceinline__ void upk2(u64 v, float& lo, float& hi) {
    asm("mov.b64 {%0, %1}, %2;" : "=f"(lo), "=f"(hi) : "l"(v));
}
__device__ __forceinline__ u64 ffma2(u64 a, u64 b, u64 c) {
#if defined(__CUDA_ARCH__) && (__CUDA_ARCH__ >= 1000)
    u64 d; asm("fma.rn.f32x2 %0, %1, %2, %3;" : "=l"(d) : "l"(a), "l"(b), "l"(c)); return d;
#else
    float al, ah, bl, bh, cl, ch;
    upk2(a, al, ah); upk2(b, bl, bh); upk2(c, cl, ch);
    return pk2(fmaf(al, bl, cl), fmaf(ah, bh, ch));
#endif
}

// A smem: physical = k*BM + (m ^ ((k>>2)<<3)).
//  - stores: bank = r[0:2] | (r[3:4]^c4) -> 32 distinct banks per warp, conflict-free
//  - reads: 4-row quads 16B-contiguous/aligned; for D>=32 all lanes of a warp share ty
//    -> full-warp broadcast LDS.128
// B smem: plain floats [k][n]; contiguous lane reads, conflict-free. {w,w} dup in regs.

template<int D>
__device__ __forceinline__ void run_stream(
    const float* __restrict__ X, const float* __restrict__ W,
    const float* __restrict__ Bias, const float* __restrict__ Gam, const float* __restrict__ Bet,
    float* __restrict__ OUT, int tile, float* __restrict__ AsF, float* __restrict__ Bk)
{
    constexpr int NX = (D >= 32) ? 32 : 16;   // n-lanes per row
    constexpr int TN = D / NX;                // 2 / 1 / 1
    constexpr int NMG = NTHR / NX;            // m-groups: 8 / 8 / 16
    constexpr int TM = BM / NMG;              // rows/thread: 16 / 16 / 8
    constexpr int NB = (BK * D) / NTHR;       // B floats/thread: 4 / 2 / 1
    const int tid = threadIdx.x;
    const int tx  = tid & (NX - 1);
    const int ty  = tid / NX;                 // rows ty*TM .. ty*TM+TM-1
    const int r0  = tid >> 2;                 // A-load row base (+64)
    const int c4  = tid & 3;                  // A-load k-chunk
    const float* __restrict__ Ablk = X + (size_t)tile * BM * HIN;

    float4 va[2];
    float  vb[NB];
    u64 acc[TM / 2][TN];
#pragma unroll
    for (int i = 0; i < TM / 2; ++i)
#pragma unroll
        for (int j = 0; j < TN; ++j) acc[i][j] = 0ull;

    // ---- prologue: load tile 0 ----
#pragma unroll
    for (int p = 0; p < 2; ++p)
        va[p] = *(const float4*)(Ablk + (size_t)(r0 + p * 64) * HIN + c4 * 4);
#pragma unroll
    for (int q = 0; q < NB; ++q) vb[q] = W[tid + q * NTHR];

    for (int t = 0; t < NT; ++t) {
        // store staged tile to smem
#pragma unroll
        for (int p = 0; p < 2; ++p) {
            const int r = r0 + p * 64;
            const float* vp = (const float*)&va[p];
#pragma unroll
            for (int u = 0; u < 4; ++u)
                AsF[(c4 * 4 + u) * BM + (r ^ (c4 << 3))] = vp[u];
        }
#pragma unroll
        for (int q = 0; q < NB; ++q) Bk[tid + q * NTHR] = vb[q];
        __syncthreads();

        // prefetch next tile into registers (hidden under compute)
        const bool more = (t + 1 < NT);
        const int k0n = (t + 1) * BK;
        if (more) {
#pragma unroll
            for (int p = 0; p < 2; ++p)
                va[p] = *(const float4*)(Ablk + (size_t)(r0 + p * 64) * HIN + k0n + c4 * 4);
#pragma unroll
            for (int q = 0; q < NB; ++q) vb[q] = W[(size_t)k0n * D + tid + q * NTHR];
        }

        // compute BK k-steps
#pragma unroll
        for (int k = 0; k < BK; ++k) {
            const int msk = (k >> 2) << 3;
            // B: contiguous read + register duplication
            u64 bd[TN];
            if constexpr (TN == 2) {
                float2 b2 = *(const float2*)(Bk + k * D + tx * 2);
                bd[0] = pk2(b2.x, b2.x); bd[1] = pk2(b2.y, b2.y);
            } else {
                float b1 = Bk[k * D + tx];
                bd[0] = pk2(b1, b1);
            }
            // A: TM rows = TM/4 broadcast LDS.128
            const float* Ar = AsF + k * BM;
            u64 ap[TM / 2];
#pragma unroll
            for (int i = 0; i < TM / 4; ++i) {
                ulonglong2 a = *(const ulonglong2*)(Ar + ((ty * TM + i * 4) ^ msk));
                ap[i * 2] = a.x; ap[i * 2 + 1] = a.y;
            }
#pragma unroll
            for (int j = 0; j < TN; ++j)
#pragma unroll
                for (int i = 0; i < TM / 2; ++i)
                    acc[i][j] = ffma2(ap[i], bd[j], acc[i][j]);
        }
        __syncthreads();
    }

    // ---- fused epilogue: bias + exact GELU + LayerNorm over D + gamma/beta ----
    float bias[TN], gam[TN], bet[TN];
#pragma unroll
    for (int j = 0; j < TN; ++j) {
        int n = tx * TN + j;
        bias[j] = __ldg(Bias + n); gam[j] = __ldg(Gam + n); bet[j] = __ldg(Bet + n);
    }
    const float invD = 1.0f / (float)D;
#pragma unroll
    for (int r = 0; r < TM; ++r) {
        float v[TN];
#pragma unroll
        for (int j = 0; j < TN; ++j) {
            float lo, hi; upk2(acc[r >> 1][j], lo, hi);
            v[j] = (r & 1) ? hi : lo;
        }
        float s = 0.f, s2 = 0.f;
#pragma unroll
        for (int j = 0; j < TN; ++j) {
            float x = v[j] + bias[j];
            float g = 0.5f * x * (1.0f + erff(x * 0.7071067811865475f));  // exact GELU
            v[j] = g; s += g; s2 += g * g;
        }
        // row's D columns live in NX consecutive lanes (tx = lane & (NX-1))
#pragma unroll
        for (int o = NX / 2; o >= 1; o >>= 1) {
            s  += __shfl_xor_sync(0xffffffffu, s,  o);
            s2 += __shfl_xor_sync(0xffffffffu, s2, o);
        }
        float mu  = s * invD;
        float var = fmaxf(s2 * invD - mu * mu, 0.0f);
        float rs  = rsqrtf(var + 1e-5f);
        int m = tile * BM + ty * TM + r;
        float* dst = OUT + (size_t)m * D + tx * TN;
#pragma unroll
        for (int j = 0; j < TN; ++j) v[j] = (v[j] - mu) * rs * gam[j] + bet[j];
        if constexpr (TN == 2) *(float2*)dst = make_float2(v[0], v[1]);
        else                   dst[0] = v[0];
    }
}

__global__ void __launch_bounds__(NTHR, 2) fused_gemm_gelu_ln(
    const float* __restrict__ x0, const float* __restrict__ w0, const float* __restrict__ b0,
    const float* __restrict__ g0, const float* __restrict__ t0,
    const float* __restrict__ x1, const float* __restrict__ w1, const float* __restrict__ b1,
    const float* __restrict__ g1, const float* __restrict__ t1,
    const float* __restrict__ x2, const float* __restrict__ w2, const float* __restrict__ b2,
    const float* __restrict__ g2, const float* __restrict__ t2,
    const float* __restrict__ x3, const float* __restrict__ w3, const float* __restrict__ b3,
    const float* __restrict__ g3, const float* __restrict__ t3,
    float* __restrict__ out)
{
    __shared__ __align__(16) float AsF[BK * BM];   // 8 KB, transposed+swizzled A tile
    __shared__ __align__(16) float Bk[BK * 64];    // 4 KB, plain B tile (max D=64)
    const int s    = blockIdx.x & 3;               // interleave streams for balance
    const int tile = blockIdx.x >> 2;              // 64 tiles per stream
    if (s == 0)      run_stream<64>(x0, w0, b0, g0, t0, out,           tile, AsF, Bk);
    else if (s == 1) run_stream<32>(x1, w1, b1, g1, t1, out + 524288,  tile, AsF, Bk);
    else if (s == 2) run_stream<32>(x2, w2, b2, g2, t2, out + 786432,  tile, AsF, Bk);
    else             run_stream<16>(x3, w3, b3, g3, t3, out + 1048576, tile, AsF, Bk);
}

extern "C" void kernel_launch(void* const* d_in, const int* in_sizes, int n_in,
                              void* d_out, int out_size)
{
    const float* x0 = (const float*)d_in[0];
    const float* w0 = (const float*)d_in[1];
    const float* b0 = (const float*)d_in[2];
    const float* g0 = (const float*)d_in[3];
    const float* t0 = (const float*)d_in[4];
    const float* x1 = (const float*)d_in[5];
    const float* w1 = (const float*)d_in[6];
    const float* b1 = (const float*)d_in[7];
    const float* g1 = (const float*)d_in[8];
    const float* t1 = (const float*)d_in[9];
    const float* x2 = (const float*)d_in[10];
    const float* w2 = (const float*)d_in[11];
    const float* b2 = (const float*)d_in[12];
    const float* g2 = (const float*)d_in[13];
    const float* t2 = (const float*)d_in[14];
    const float* x3 = (const float*)d_in[15];
    const float* w3 = (const float*)d_in[16];
    const float* b3 = (const float*)d_in[17];
    const float* g3 = (const float*)d_in[18];
    const float* t3 = (const float*)d_in[19];
    float* out = (float*)d_out;

    // grid: 4 streams x (8192/128) tiles, stream-interleaved; 256-thread blocks
    fused_gemm_gelu_ln<<<256, NTHR>>>(
        x0, w0, b0, g0, t0,
        x1, w1, b1, g1, t1,
        x2, w2, b2, g2, t2,
        x3, w3, b3, g3, t3,
        out);
}

// round 11
// speedup vs baseline: 2.3498x; 1.4287x over previous
#include <cuda_runtime.h>
#include <math.h>

#define HIN 1536
#define BM  128
#define BK  16
#define NT  (HIN / BK)   // 96 k-tiles
#define NTHR 128

using u64 = unsigned long long;

__device__ __forceinline__ u64 pk2(float lo, float hi) {
    u64 r; asm("mov.b64 %0, {%1, %2};" : "=l"(r) : "f"(lo), "f"(hi)); return r;
}
__device__ __forceinline__ void upk2(u64 v, float& lo, float& hi) {
    asm("mov.b64 {%0, %1}, %2;" : "=f"(lo), "=f"(hi) : "l"(v));
}
__device__ __forceinline__ u64 ffma2(u64 a, u64 b, u64 c) {
#if defined(__CUDA_ARCH__) && (__CUDA_ARCH__ >= 1000)
    u64 d; asm("fma.rn.f32x2 %0, %1, %2, %3;" : "=l"(d) : "l"(a), "l"(b), "l"(c)); return d;
#else
    float al, ah, bl, bh, cl, ch;
    upk2(a, al, ah); upk2(b, bl, bh); upk2(c, cl, ch);
    return pk2(fmaf(al, bl, cl), fmaf(ah, bh, ch));
#endif
}

// A smem: physical = k*BM + (m ^ ((k>>2)<<3)). Stores conflict-free (32 banks),
// reads: 4 ty-groups/warp at rows {0,8,16,24} mod 32 -> disjoint bank-quads.
// B smem: D=64 uses padded layout phys = n + ((n>>5)<<2), row stride 72 words
// so lanes tx and tx+4 (32 words apart) land in different banks. D<=32 rows
// span <= 32 banks naturally -> no pad.

template<int D> __device__ __forceinline__ int bswz(int n) {
    if constexpr (D == 64) return n + ((n >> 5) << 2);
    else return n;
}
template<int D> constexpr int BROW = (D == 64) ? 72 : D;

template<int D>
__device__ __forceinline__ void run_stream(
    const float* __restrict__ X, const float* __restrict__ W,
    const float* __restrict__ Bias, const float* __restrict__ Gam, const float* __restrict__ Bet,
    float* __restrict__ OUT, int tile, float* __restrict__ AsF, float* __restrict__ Bk)
{
    constexpr int TN = D / 8;             // 8 / 4 / 2
    constexpr int TM = 8;                 // rows per thread
    constexpr int NB = (BK * D) / NTHR;   // B floats per thread: 8 / 4 / 2
    const int tid = threadIdx.x;
    const int tx  = tid & 7;              // n-group (8): cols tx*TN .. tx*TN+TN-1
    const int ty  = tid >> 3;             // m-group (16): rows ty*8 .. ty*8+7
    const int r0  = tid >> 2;             // A-load row base (+p*32)
    const int c4  = tid & 3;              // A-load k-chunk
    const float* __restrict__ Ablk = X + (size_t)tile * BM * HIN;

    float4 va[4];
    float  vb[NB];
    u64 acc[TM / 2][TN];
#pragma unroll
    for (int i = 0; i < TM / 2; ++i)
#pragma unroll
        for (int j = 0; j < TN; ++j) acc[i][j] = 0ull;

    // ---- prologue: load tile 0 ----
#pragma unroll
    for (int p = 0; p < 4; ++p)
        va[p] = *(const float4*)(Ablk + (size_t)(r0 + p * 32) * HIN + c4 * 4);
#pragma unroll
    for (int q = 0; q < NB; ++q) vb[q] = W[tid + q * NTHR];

    for (int t = 0; t < NT; ++t) {
        // store staged tile to smem
#pragma unroll
        for (int p = 0; p < 4; ++p) {
            const int r = r0 + p * 32;
            const float* vp = (const float*)&va[p];
#pragma unroll
            for (int u = 0; u < 4; ++u)
                AsF[(c4 * 4 + u) * BM + (r ^ (c4 << 3))] = vp[u];
        }
#pragma unroll
        for (int q = 0; q < NB; ++q) {
            int idx = tid + q * NTHR;
            int kk = idx / D, nn = idx % D;
            Bk[kk * BROW<D> + bswz<D>(nn)] = vb[q];
        }
        __syncthreads();

        // prefetch next tile into registers (hidden under compute)
        const bool more = (t + 1 < NT);
        const int k0n = (t + 1) * BK;
        if (more) {
#pragma unroll
            for (int p = 0; p < 4; ++p)
                va[p] = *(const float4*)(Ablk + (size_t)(r0 + p * 32) * HIN + k0n + c4 * 4);
#pragma unroll
            for (int q = 0; q < NB; ++q) vb[q] = W[(size_t)k0n * D + tid + q * NTHR];
        }

        // compute BK k-steps
#pragma unroll
        for (int k = 0; k < BK; ++k) {
            const int msk = (k >> 2) << 3;
            // B: conflict-free reads (padded for D=64), duplicate in registers
            u64 bd[TN];
            const float* brow = Bk + k * BROW<D> + bswz<D>(tx * TN);
            if constexpr (TN == 8) {
                float4 b0 = *(const float4*)(brow);
                float4 b1 = *(const float4*)(brow + 4);
                bd[0] = pk2(b0.x, b0.x); bd[1] = pk2(b0.y, b0.y);
                bd[2] = pk2(b0.z, b0.z); bd[3] = pk2(b0.w, b0.w);
                bd[4] = pk2(b1.x, b1.x); bd[5] = pk2(b1.y, b1.y);
                bd[6] = pk2(b1.z, b1.z); bd[7] = pk2(b1.w, b1.w);
            } else if constexpr (TN == 4) {
                float4 b0 = *(const float4*)(brow);
                bd[0] = pk2(b0.x, b0.x); bd[1] = pk2(b0.y, b0.y);
                bd[2] = pk2(b0.z, b0.z); bd[3] = pk2(b0.w, b0.w);
            } else {
                float2 b0 = *(const float2*)(brow);
                bd[0] = pk2(b0.x, b0.x); bd[1] = pk2(b0.y, b0.y);
            }
            // A: 8 rows = 2 LDS.128 (4 bcast-groups/warp, disjoint banks)
            const float* Ar = AsF + k * BM;
            ulonglong2 a0 = *(const ulonglong2*)(Ar + ((ty * 8)     ^ msk));
            ulonglong2 a1 = *(const ulonglong2*)(Ar + ((ty * 8 + 4) ^ msk));
            u64 ap[4] = { a0.x, a0.y, a1.x, a1.y };
#pragma unroll
            for (int j = 0; j < TN; ++j)
#pragma unroll
                for (int i = 0; i < 4; ++i)
                    acc[i][j] = ffma2(ap[i], bd[j], acc[i][j]);
        }
        __syncthreads();
    }

    // ---- fused epilogue: bias + exact GELU + LayerNorm over D + gamma/beta ----
    float bias[TN], gam[TN], bet[TN];
#pragma unroll
    for (int j = 0; j < TN; ++j) {
        int n = tx * TN + j;
        bias[j] = __ldg(Bias + n); gam[j] = __ldg(Gam + n); bet[j] = __ldg(Bet + n);
    }
    const float invD = 1.0f / (float)D;
#pragma unroll
    for (int r = 0; r < TM; ++r) {
        float v[TN];
#pragma unroll
        for (int j = 0; j < TN; ++j) {
            float lo, hi; upk2(acc[r >> 1][j], lo, hi);
            v[j] = (r & 1) ? hi : lo;
        }
        float s = 0.f, s2 = 0.f;
#pragma unroll
        for (int j = 0; j < TN; ++j) {
            float x = v[j] + bias[j];
            float g = 0.5f * x * (1.0f + erff(x * 0.7071067811865475f));  // exact GELU
            v[j] = g; s += g; s2 += g * g;
        }
        // row's D columns live in 8 consecutive lanes (tx = lane & 7)
#pragma unroll
        for (int o = 4; o >= 1; o >>= 1) {
            s  += __shfl_xor_sync(0xffffffffu, s,  o);
            s2 += __shfl_xor_sync(0xffffffffu, s2, o);
        }
        float mu  = s * invD;
        float var = fmaxf(s2 * invD - mu * mu, 0.0f);
        float rs  = rsqrtf(var + 1e-5f);
        int m = tile * BM + ty * TM + r;
        float* dst = OUT + (size_t)m * D + tx * TN;
#pragma unroll
        for (int j = 0; j < TN; ++j) v[j] = (v[j] - mu) * rs * gam[j] + bet[j];
        if constexpr (TN == 8) {
            *(float4*)dst       = make_float4(v[0], v[1], v[2], v[3]);
            *(float4*)(dst + 4) = make_float4(v[4], v[5], v[6], v[7]);
        } else if constexpr (TN == 4) {
            *(float4*)dst = make_float4(v[0], v[1], v[2], v[3]);
        } else {
            *(float2*)dst = make_float2(v[0], v[1]);
        }
    }
}

__global__ void __launch_bounds__(NTHR, 2) fused_gemm_gelu_ln(
    const float* __restrict__ x0, const float* __restrict__ w0, const float* __restrict__ b0,
    const float* __restrict__ g0, const float* __restrict__ t0,
    const float* __restrict__ x1, const float* __restrict__ w1, const float* __restrict__ b1,
    const float* __restrict__ g1, const float* __restrict__ t1,
    const float* __restrict__ x2, const float* __restrict__ w2, const float* __restrict__ b2,
    const float* __restrict__ g2, const float* __restrict__ t2,
    const float* __restrict__ x3, const float* __restrict__ w3, const float* __restrict__ b3,
    const float* __restrict__ g3, const float* __restrict__ t3,
    float* __restrict__ out)
{
    __shared__ __align__(16) float AsF[BK * BM];       // 8 KB, transposed+swizzled A
    __shared__ __align__(16) float Bk[BK * 72];        // 4.5 KB, padded B (max D=64)

    // LPT ordering: D=64 blocks (longest) first, D=16 last — shorter blocks
    // pack the second wave behind the long D64 blocks.
    const int bid  = blockIdx.x;
    const int s    = bid >> 6;       // 0..3
    const int tile = bid & 63;       // 64 tiles per stream
    if (s == 0)      run_stream<64>(x0, w0, b0, g0, t0, out,           tile, AsF, Bk);
    else if (s == 1) run_stream<32>(x1, w1, b1, g1, t1, out + 524288,  tile, AsF, Bk);
    else if (s == 2) run_stream<32>(x2, w2, b2, g2, t2, out + 786432,  tile, AsF, Bk);
    else             run_stream<16>(x3, w3, b3, g3, t3, out + 1048576, tile, AsF, Bk);
}

extern "C" void kernel_launch(void* const* d_in, const int* in_sizes, int n_in,
                              void* d_out, int out_size)
{
    const float* x0 = (const float*)d_in[0];
    const float* w0 = (const float*)d_in[1];
    const float* b0 = (const float*)d_in[2];
    const float* g0 = (const float*)d_in[3];
    const float* t0 = (const float*)d_in[4];
    const float* x1 = (const float*)d_in[5];
    const float* w1 = (const float*)d_in[6];
    const float* b1 = (const float*)d_in[7];
    const float* g1 = (const float*)d_in[8];
    const float* t1 = (const float*)d_in[9];
    const float* x2 = (const float*)d_in[10];
    const float* w2 = (const float*)d_in[11];
    const float* b2 = (const float*)d_in[12];
    const float* g2 = (const float*)d_in[13];
    const float* t2 = (const float*)d_in[14];
    const float* x3 = (const float*)d_in[15];
    const float* w3 = (const float*)d_in[16];
    const float* b3 = (const float*)d_in[17];
    const float* g3 = (const float*)d_in[18];
    const float* t3 = (const float*)d_in[19];
    float* out = (float*)d_out;

    // grid: 4 streams x 64 tiles, LPT-ordered; 128-thread blocks
    fused_gemm_gelu_ln<<<256, NTHR>>>(
        x0, w0, b0, g0, t0,
        x1, w1, b1, g1, t1,
        x2, w2, b2, g2, t2,
        x3, w3, b3, g3, t3,
        out);
}